// round 10
// baseline (speedup 1.0000x reference)
#include <cuda_runtime.h>
#include <cuda_fp16.h>
#include <math.h>
#include <cstdint>

#define BB 16
#define CC 512
#define SS 4096
#define HH 8
#define DD 64
#define QKV 1536
#define NSTG 3
#define NSEG 16
#define CSEG 256

// ---------------- scratch (static __device__, allocation-free) ----------------
__device__ __half g_wqh[QKV * CC];
__device__ __half g_woh[CC * CC];
__device__ __half g_xh[(size_t)BB * SS * CC];          // 67 MB
__device__ __half g_qkvh[(size_t)BB * QKV * SS];       // v region used
__device__ __half g_ekh[(size_t)BB * 512 * SS];        // 67 MB  exp(k) fp16
__device__ float  g_ksump[64][BB * 512];               // 2 MB   k row-sum partials
__device__ float  g_ksum[BB * 512];
__device__ float  g_qsum[(size_t)BB * HH * SS];        // 2 MB   q col sums (per n)
__device__ float  g_ctxp[NSEG][BB * HH * DD * DD];
__device__ __half g_ctxh[BB * HH * DD * DD];
__device__ __half g_qs[(size_t)BB * HH * SS * DD];     // 67 MB  exp(q)^T [bh][n][d]
__device__ __half g_mh[(size_t)BB * SS * CC];          // 67 MB  midT fp16

// ---------------- helpers ----------------
__device__ __forceinline__ uint32_t smem_u32(const void* p) {
    uint32_t a;
    asm("{ .reg .u64 t; cvta.to.shared.u64 t, %1; cvt.u32.u64 %0, t; }" : "=r"(a) : "l"(p));
    return a;
}
#define CP_ASYNC(dst, src) \
    asm volatile("cp.async.cg.shared.global [%0], [%1], 16;" :: "r"(dst), "l"(src) : "memory")
#define CP_COMMIT() asm volatile("cp.async.commit_group;" ::: "memory")
#define CP_WAIT(n)  asm volatile("cp.async.wait_group %0;" :: "n"(n) : "memory")
#define LDSM4(R, addr) \
    asm volatile("ldmatrix.sync.aligned.m8n8.x4.shared.b16 {%0,%1,%2,%3}, [%4];" \
        : "=r"((R)[0]), "=r"((R)[1]), "=r"((R)[2]), "=r"((R)[3]) : "r"(addr))

__device__ __forceinline__ void mma16(float* c, const uint32_t* a, const uint32_t* b) {
    asm volatile(
        "mma.sync.aligned.m16n8k16.row.col.f32.f16.f16.f32 "
        "{%0,%1,%2,%3},{%4,%5,%6,%7},{%8,%9},{%0,%1,%2,%3};"
        : "+f"(c[0]), "+f"(c[1]), "+f"(c[2]), "+f"(c[3])
        : "r"(a[0]), "r"(a[1]), "r"(a[2]), "r"(a[3]), "r"(b[0]), "r"(b[1]));
}

// ---------------------------------------------------------------------------
__global__ void k_prep_wq(const float* __restrict__ w, const float* __restrict__ g1) {
    int i = blockIdx.x * 256 + threadIdx.x;
    g_wqh[i] = __float2half_rn(w[i] * g1[i & (CC - 1)]);
}
__global__ void k_prep_wo(const float* __restrict__ w) {
    int i = blockIdx.x * 256 + threadIdx.x;
    g_woh[i] = __float2half_rn(w[i]);
}

// ---------------------------------------------------------------------------
// normT: xh[b][s][c] = fp16(x[b][c][s]*r[b,s])
// ---------------------------------------------------------------------------
__global__ void k_normT(const float* __restrict__ x) {
    extern __shared__ float sm[];
    float* tile = sm;                  // [512][33]
    float* rr = sm + 512 * 33;
    int b = blockIdx.y, s0 = blockIdx.x * 32;
    int t = threadIdx.x;
    const float* xp = x + (size_t)b * CC * SS + s0;

    for (int i = t; i < 512 * 32; i += 256) {
        int c = i >> 5, sl = i & 31;
        tile[c * 33 + sl] = xp[(size_t)c * SS + sl];
    }
    __syncthreads();

    int sl = t >> 3, part = t & 7;
    float acc = 0.f;
    for (int c = part; c < 512; c += 8) {
        float v = tile[c * 33 + sl];
        acc += v * v;
    }
#pragma unroll
    for (int o = 4; o; o >>= 1) acc += __shfl_down_sync(0xFFFFFFFFu, acc, o);
    if (part == 0) rr[sl] = 22.62741699796952f / fmaxf(sqrtf(acc), 1e-12f);
    __syncthreads();

    float rv = rr[sl];
    __half* op = g_xh + ((size_t)b * SS + s0 + sl) * CC;
    for (int c0 = part * 64; c0 < part * 64 + 64; c0 += 8) {
        __half h[8];
#pragma unroll
        for (int j = 0; j < 8; j++) h[j] = __float2half_rn(tile[(c0 + j) * 33 + sl] * rv);
        *(uint4*)(op + c0) = *(uint4*)h;
    }
}

// ---------------------------------------------------------------------------
// K1: qkv GEMM, CTA tile 128(M)x256(N), BK=64, 8 warps of 64x64, 3-stage.
// Fused per-section epilogue (q: exp+transpose+colsum / k: exp+rowsum / v: fp16).
// ---------------------------------------------------------------------------
__global__ __launch_bounds__(256, 1)
void k_hgemm() {
    extern __shared__ char smc[];
    uint32_t sbase = smem_u32(smc);
    const int STG = 49152;                 // A 16KB + B 32KB

    int tid = threadIdx.x, lane = tid & 31, wid = tid >> 5;
    int b = blockIdx.z, m0 = blockIdx.y * 128, n0 = blockIdx.x * 256;
    const __half* Ab = g_wqh + (size_t)m0 * CC;
    const __half* Bb = g_xh + (size_t)b * SS * CC + (size_t)n0 * CC;

    const int NC = CC / 64;

    auto issue = [&](int kc, int buf) {
        const __half* Asrc = Ab + kc * 64;
        const __half* Bsrc = Bb + kc * 64;
        uint32_t base = sbase + buf * STG;
#pragma unroll
        for (int it = 0; it < 4; it++) {       // A: 128 rows x 8 chunks
            int id = it * 256 + tid;
            int row = id >> 3, j = id & 7;
            CP_ASYNC(base + row * 128 + ((j ^ (row & 7)) << 4),
                     Asrc + (size_t)row * CC + j * 8);
        }
#pragma unroll
        for (int it = 0; it < 8; it++) {       // B: 256 rows x 8 chunks
            int id = it * 256 + tid;
            int row = id >> 3, j = id & 7;
            CP_ASYNC(base + 16384 + row * 128 + ((j ^ (row & 7)) << 4),
                     Bsrc + (size_t)row * CC + j * 8);
        }
    };

#pragma unroll
    for (int s = 0; s < NSTG - 1; s++) { issue(s, s); CP_COMMIT(); }

    int wm = (wid & 1) * 64, wn = (wid >> 1) * 64;
    int rA = wm + (lane & 7) + ((lane >> 3) & 1) * 8;
    int cA = (lane >> 4);
    int rB = wn + (lane & 7) + ((lane >> 4) & 1) * 8;
    int cB = (lane >> 3) & 1;
    int swA = rA & 7, swB = rB & 7;

    float acc[4][8][4] = {};

    for (int kc = 0; kc < NC; kc++) {
        CP_WAIT(NSTG - 2);
        __syncthreads();
        if (kc + NSTG - 1 < NC) issue(kc + NSTG - 1, (kc + NSTG - 1) % NSTG);
        CP_COMMIT();
        uint32_t bufA = sbase + (kc % NSTG) * STG;
        uint32_t bufB = bufA + 16384;
#pragma unroll
        for (int ks = 0; ks < 4; ks++) {
            uint32_t a[4][4], bf[4][4];
            uint32_t kchA = ((uint32_t)(ks * 2 + cA) ^ swA) << 4;
            uint32_t kchB = ((uint32_t)(ks * 2 + cB) ^ swB) << 4;
#pragma unroll
            for (int mi = 0; mi < 4; mi++)
                LDSM4(a[mi], bufA + (rA + mi * 16) * 128 + kchA);
#pragma unroll
            for (int p = 0; p < 4; p++)
                LDSM4(bf[p], bufB + (rB + p * 16) * 128 + kchB);
#pragma unroll
            for (int mi = 0; mi < 4; mi++)
#pragma unroll
                for (int ni = 0; ni < 8; ni++)
                    mma16(acc[mi][ni], a[mi], bf[ni >> 1] + (ni & 1) * 2);
        }
    }

    if (m0 < 512) {
        // ---- q: exp, transpose via smem, col sums ----
        __syncthreads();
        __half* qt = (__half*)smc;             // [c 0..255][r 0..127], stride 136
        float cs[16] = {};
#pragma unroll
        for (int mi = 0; mi < 4; mi++) {
#pragma unroll
            for (int ni = 0; ni < 8; ni++) {
                int c = wn + (ni >> 1) * 16 + (ni & 1) * 8 + (lane & 3) * 2;
                int r = wm + mi * 16 + (lane >> 2);
                float e0 = __expf(acc[mi][ni][0]);
                float e1 = __expf(acc[mi][ni][1]);
                float e2 = __expf(acc[mi][ni][2]);
                float e3 = __expf(acc[mi][ni][3]);
                qt[c * 136 + r]           = __float2half_rn(e0);
                qt[(c + 1) * 136 + r]     = __float2half_rn(e1);
                qt[c * 136 + r + 8]       = __float2half_rn(e2);
                qt[(c + 1) * 136 + r + 8] = __float2half_rn(e3);
                cs[ni * 2]     += e0 + e2;
                cs[ni * 2 + 1] += e1 + e3;
            }
        }
#pragma unroll
        for (int j = 0; j < 16; j++)
#pragma unroll
            for (int o = 4; o <= 16; o <<= 1)
                cs[j] += __shfl_xor_sync(0xFFFFFFFFu, cs[j], o);
        int head = (m0 >> 6) + (wid & 1);
        if ((lane >> 2) == 0) {
            float* qsump = g_qsum + (size_t)(b * HH + head) * SS + n0;
#pragma unroll
            for (int j = 0; j < 16; j++) {
                int ni = j >> 1;
                int c = wn + (ni >> 1) * 16 + (ni & 1) * 8 + (lane & 3) * 2 + (j & 1);
                qsump[c] = cs[j];
            }
        }
        __syncthreads();
        int n = tid;
#pragma unroll
        for (int hh = 0; hh < 2; hh++) {
            const uint4* src = (const uint4*)(qt + n * 136 + hh * 64);
            __half* dst = g_qs + ((size_t)(b * HH + (m0 >> 6) + hh) * SS + n0 + n) * 64;
#pragma unroll
            for (int j = 0; j < 8; j++) ((uint4*)dst)[j] = src[j];
        }
    } else if (m0 < 1024) {
        // ---- k: exp store + row-sum partials ----
        float rs[8] = {};
        __half* ekd = g_ekh + (size_t)(b * 512 + m0 - 512) * SS + n0;
#pragma unroll
        for (int mi = 0; mi < 4; mi++) {
            int r = wm + mi * 16 + (lane >> 2);
#pragma unroll
            for (int ni = 0; ni < 8; ni++) {
                int c = wn + (ni >> 1) * 16 + (ni & 1) * 8 + (lane & 3) * 2;
                float e0 = __expf(acc[mi][ni][0]);
                float e1 = __expf(acc[mi][ni][1]);
                float e2 = __expf(acc[mi][ni][2]);
                float e3 = __expf(acc[mi][ni][3]);
                *(__half2*)(ekd + (size_t)r * SS + c) = __floats2half2_rn(e0, e1);
                *(__half2*)(ekd + (size_t)(r + 8) * SS + c) = __floats2half2_rn(e2, e3);
                rs[mi * 2]     += e0 + e1;
                rs[mi * 2 + 1] += e2 + e3;
            }
        }
#pragma unroll
        for (int j = 0; j < 8; j++) {
            rs[j] += __shfl_xor_sync(0xFFFFFFFFu, rs[j], 1);
            rs[j] += __shfl_xor_sync(0xFFFFFFFFu, rs[j], 2);
        }
        if ((lane & 3) == 0) {
            int slot = blockIdx.x * 4 + (wid >> 1);
            float* kp = g_ksump[slot] + b * 512 + (m0 - 512) + wm;
#pragma unroll
            for (int j = 0; j < 8; j++)
                kp[(j >> 1) * 16 + (lane >> 2) + (j & 1) * 8] = rs[j];
        }
    } else {
        // ---- v: plain fp16 ----
        __half* Cd = g_qkvh + (size_t)b * QKV * SS;
#pragma unroll
        for (int mi = 0; mi < 4; mi++) {
            int r0 = m0 + wm + mi * 16 + (lane >> 2);
#pragma unroll
            for (int ni = 0; ni < 8; ni++) {
                int c = n0 + wn + (ni >> 1) * 16 + (ni & 1) * 8 + (lane & 3) * 2;
                *(__half2*)(Cd + (size_t)r0 * SS + c) =
                    __floats2half2_rn(acc[mi][ni][0], acc[mi][ni][1]);
                *(__half2*)(Cd + (size_t)(r0 + 8) * SS + c) =
                    __floats2half2_rn(acc[mi][ni][2], acc[mi][ni][3]);
            }
        }
    }
}

// ---------------------------------------------------------------------------
// ksum finish: sum the 64 partial slots
// ---------------------------------------------------------------------------
__global__ void k_ksumf() {
    int i = blockIdx.x * 256 + threadIdx.x;        // 8192
    float s = 0.f;
#pragma unroll 8
    for (int t = 0; t < 64; t++) s += g_ksump[t][i];
    g_ksum[i] = s;
}

// ---------------------------------------------------------------------------
// ctx_mma: partial ctxT[e][d] = sum_{n in seg} v[e,n] * ek[d,n]
// ---------------------------------------------------------------------------
__global__ __launch_bounds__(128, 3)
void k_ctx_mma() {
    extern __shared__ char smc[];
    int seg = blockIdx.x, h = blockIdx.y, b = blockIdx.z;
    int n0 = seg * CSEG;
    const __half* vp = g_qkvh + ((size_t)b * QKV + 1024 + h * 64) * SS + n0;
    const __half* ekp = g_ekh + (size_t)(b * 512 + h * 64) * SS + n0;

    uint32_t sA = smem_u32(smc), sB = sA + 32768;
    int tid = threadIdx.x, lane = tid & 31, wid = tid >> 5;

#pragma unroll
    for (int it = 0; it < 16; it++) {
        int id = it * 128 + tid;
        int row = id >> 5, j = id & 31;
        uint32_t soff = row * 512 + (((uint32_t)(j ^ (row & 7))) << 4);
        CP_ASYNC(sA + soff, vp + (size_t)row * SS + j * 8);
        CP_ASYNC(sB + soff, ekp + (size_t)row * SS + j * 8);
    }
    CP_COMMIT();
    CP_WAIT(0);
    __syncthreads();

    int rA = wid * 16 + (lane & 7) + ((lane >> 3) & 1) * 8;
    int cA = lane >> 4;
    int rB = (lane & 7) + ((lane >> 4) & 1) * 8;
    int cB = (lane >> 3) & 1;
    int swA = rA & 7, swB = rB & 7;

    float acc[8][4] = {};
#pragma unroll
    for (int ks = 0; ks < 16; ks++) {
        uint32_t a[4], bf[4][4];
        LDSM4(a, sA + rA * 512 + (((uint32_t)(ks * 2 + cA) ^ swA) << 4));
#pragma unroll
        for (int p = 0; p < 4; p++)
            LDSM4(bf[p], sB + (rB + p * 16) * 512 + (((uint32_t)(ks * 2 + cB) ^ swB) << 4));
#pragma unroll
        for (int p = 0; p < 4; p++)
#pragma unroll
            for (int hf = 0; hf < 2; hf++)
                mma16(acc[p * 2 + hf], a, bf[p] + hf * 2);
    }

    float* cp = g_ctxp[seg] + (size_t)(b * HH + h) * 4096;
    int r0 = wid * 16 + (lane >> 2);
#pragma unroll
    for (int ni = 0; ni < 8; ni++) {
        int d = (ni >> 1) * 16 + (ni & 1) * 8 + (lane & 3) * 2;
        *(float2*)(cp + r0 * 64 + d) = make_float2(acc[ni][0], acc[ni][1]);
        *(float2*)(cp + (r0 + 8) * 64 + d) = make_float2(acc[ni][2], acc[ni][3]);
    }
}

// ---------------------------------------------------------------------------
// ctx finish: ctxh[bh][e][d] = fp16( 0.125/ksum[d] * sum_seg ctxp )
// ---------------------------------------------------------------------------
__global__ void k_ctx_fin() {
    int i = blockIdx.x * 256 + threadIdx.x;
    int bh = i >> 12, d = i & 63;
    float s = 0.f;
#pragma unroll
    for (int p = 0; p < NSEG; p++) s += g_ctxp[p][i];
    float inv = 0.125f / g_ksum[(bh >> 3) * 512 + (bh & 7) * 64 + d];
    g_ctxh[i] = __float2half_rn(s * inv);
}

// ---------------------------------------------------------------------------
// apply_mma: mh[b][n][h*64+e] = (1/qsum[n]) * sum_d eq[bh][n][d] * ctxh[bh][e][d]
// ---------------------------------------------------------------------------
__global__ __launch_bounds__(256, 2)
void k_apply_mma() {
    __shared__ __align__(16) char smc[24576];
    int nt = blockIdx.x, h = blockIdx.y, b = blockIdx.z;
    int n0 = nt * 128;
    const __half* Aq = g_qs + ((size_t)(b * HH + h) * SS + n0) * 64;
    const __half* Bc = g_ctxh + (size_t)(b * HH + h) * 4096;
    const float* qsp = g_qsum + (size_t)(b * HH + h) * SS + n0;

    uint32_t sA = smem_u32(smc), sB = sA + 16384;
    int tid = threadIdx.x, lane = tid & 31, wid = tid >> 5;

#pragma unroll
    for (int it = 0; it < 4; it++) {
        int id = it * 256 + tid;
        int row = id >> 3, j = id & 7;
        CP_ASYNC(sA + row * 128 + ((uint32_t)(j ^ (row & 7)) << 4),
                 Aq + (size_t)row * 64 + j * 8);
    }
#pragma unroll
    for (int it = 0; it < 2; it++) {
        int id = it * 256 + tid;
        int row = id >> 3, j = id & 7;
        CP_ASYNC(sB + row * 128 + ((uint32_t)(j ^ (row & 7)) << 4),
                 Bc + (size_t)row * 64 + j * 8);
    }
    CP_COMMIT();
    CP_WAIT(0);
    __syncthreads();

    int wm = (wid >> 1) * 32, wn = (wid & 1) * 32;
    int rA = wm + (lane & 7) + ((lane >> 3) & 1) * 8;
    int cA = lane >> 4;
    int rB = wn + (lane & 7) + ((lane >> 4) & 1) * 8;
    int cB = (lane >> 3) & 1;
    int swA = rA & 7, swB = rB & 7;

    float acc[2][4][4] = {};
#pragma unroll
    for (int ks = 0; ks < 4; ks++) {
        uint32_t a[2][4], bf[2][4];
        uint32_t kchA = ((uint32_t)(ks * 2 + cA) ^ swA) << 4;
        uint32_t kchB = ((uint32_t)(ks * 2 + cB) ^ swB) << 4;
#pragma unroll
        for (int mi = 0; mi < 2; mi++)
            LDSM4(a[mi], sA + (rA + mi * 16) * 128 + kchA);
#pragma unroll
        for (int p = 0; p < 2; p++)
            LDSM4(bf[p], sB + (rB + p * 16) * 128 + kchB);
#pragma unroll
        for (int mi = 0; mi < 2; mi++)
#pragma unroll
            for (int ni = 0; ni < 4; ni++)
                mma16(acc[mi][ni], a[mi], bf[ni >> 1] + (ni & 1) * 2);
    }

    __half* outp = g_mh + (size_t)b * SS * CC;
#pragma unroll
    for (int mi = 0; mi < 2; mi++) {
        int rl = wm + mi * 16 + (lane >> 2);
        float i0 = 1.f / qsp[rl];
        float i1 = 1.f / qsp[rl + 8];
        int r = n0 + rl;
#pragma unroll
        for (int ni = 0; ni < 4; ni++) {
            int c = h * 64 + wn + (ni >> 1) * 16 + (ni & 1) * 8 + (lane & 3) * 2;
            *(__half2*)(outp + (size_t)r * CC + c) =
                __floats2half2_rn(acc[mi][ni][0] * i0, acc[mi][ni][1] * i0);
            *(__half2*)(outp + (size_t)(r + 8) * CC + c) =
                __floats2half2_rn(acc[mi][ni][2] * i1, acc[mi][ni][3] * i1);
        }
    }
}

// ---------------------------------------------------------------------------
// K5: out = rmsnorm( wo @ mh^T + bias ) * gamma2
// ---------------------------------------------------------------------------
__global__ __launch_bounds__(512, 1)
void k_ogemm(const __half* __restrict__ A, const __half* __restrict__ Bg,
             float* __restrict__ out, const float* __restrict__ bias,
             const float* __restrict__ gamma2) {
    extern __shared__ char smc[];
    const int STG = 36864;
    uint32_t sbase = smem_u32(smc);
    float* colsq = (float*)(smc + 3 * STG);
    float* csc   = colsq + 64;

    int tid = threadIdx.x, lane = tid & 31, wid = tid >> 5;
    int b = blockIdx.y, n0 = blockIdx.x * 64;
    const __half* Bb = Bg + ((size_t)b * SS + n0) * CC;

    if (tid < 64) colsq[tid] = 0.f;

    auto issue = [&](int kc, int buf) {
        uint32_t base = sbase + buf * STG;
#pragma unroll
        for (int it = 0; it < 4; it++) {
            int id = it * 512 + tid;
            int row = id >> 2, j = id & 3;
            uint32_t dst = base + row * 64 + (((uint32_t)j ^ ((row >> 1) & 3)) << 4);
            CP_ASYNC(dst, A + (size_t)row * CC + kc * 32 + j * 8);
        }
        if (tid < 256) {
            int row = tid >> 2, j = tid & 3;
            uint32_t dst = base + 32768 + row * 64 + (((uint32_t)j ^ ((row >> 1) & 3)) << 4);
            CP_ASYNC(dst, Bb + (size_t)row * CC + kc * 32 + j * 8);
        }
    };

#pragma unroll
    for (int s = 0; s < NSTG - 1; s++) { issue(s, s); CP_COMMIT(); }

    int wm = (wid >> 1) * 64, wn = (wid & 1) * 32;
    int rA = wm + (lane & 7) + ((lane >> 3) & 1) * 8;
    int cA = (lane >> 4);
    int rB = wn + (lane & 7) + ((lane >> 4) & 1) * 8;
    int cB = (lane >> 3) & 1;
    int swA = (rA >> 1) & 3, swB = (rB >> 1) & 3;

    float acc[4][4][4] = {};
    const int NC = CC / 32;

    for (int kc = 0; kc < NC; kc++) {
        CP_WAIT(NSTG - 2);
        __syncthreads();
        if (kc + NSTG - 1 < NC) issue(kc + NSTG - 1, (kc + NSTG - 1) % NSTG);
        CP_COMMIT();
        uint32_t bufA = sbase + (kc % NSTG) * STG;
        uint32_t bufB = bufA + 32768;
#pragma unroll
        for (int ks = 0; ks < 2; ks++) {
            uint32_t a[4][4], bf[2][4];
            uint32_t kchA = ((uint32_t)(ks * 2 + cA) ^ swA) << 4;
            uint32_t kchB = ((uint32_t)(ks * 2 + cB) ^ swB) << 4;
#pragma unroll
            for (int mi = 0; mi < 4; mi++)
                LDSM4(a[mi], bufA + (rA + mi * 16) * 64 + kchA);
#pragma unroll
            for (int p = 0; p < 2; p++)
                LDSM4(bf[p], bufB + (rB + p * 16) * 64 + kchB);
#pragma unroll
            for (int mi = 0; mi < 4; mi++)
#pragma unroll
                for (int ni = 0; ni < 4; ni++)
                    mma16(acc[mi][ni], a[mi], bf[ni >> 1] + (ni & 1) * 2);
        }
    }

    float bi0[4], bi1[4];
#pragma unroll
    for (int mi = 0; mi < 4; mi++) {
        bi0[mi] = bias[wm + mi * 16 + (lane >> 2)];
        bi1[mi] = bias[wm + mi * 16 + (lane >> 2) + 8];
    }
#pragma unroll
    for (int ni = 0; ni < 4; ni++) {
        float l0 = 0.f, l1 = 0.f;
#pragma unroll
        for (int mi = 0; mi < 4; mi++) {
            acc[mi][ni][0] += bi0[mi]; acc[mi][ni][1] += bi0[mi];
            acc[mi][ni][2] += bi1[mi]; acc[mi][ni][3] += bi1[mi];
            l0 += acc[mi][ni][0] * acc[mi][ni][0] + acc[mi][ni][2] * acc[mi][ni][2];
            l1 += acc[mi][ni][1] * acc[mi][ni][1] + acc[mi][ni][3] * acc[mi][ni][3];
        }
#pragma unroll
        for (int o = 4; o <= 16; o <<= 1) {
            l0 += __shfl_xor_sync(0xFFFFFFFFu, l0, o);
            l1 += __shfl_xor_sync(0xFFFFFFFFu, l1, o);
        }
        if ((lane >> 2) == 0) {
            int cloc = wn + (ni >> 1) * 16 + (ni & 1) * 8 + (lane & 3) * 2;
            atomicAdd(colsq + cloc, l0);
            atomicAdd(colsq + cloc + 1, l1);
        }
    }
    __syncthreads();
    if (tid < 64)
        csc[tid] = 22.62741699796952f / fmaxf(sqrtf(colsq[tid]), 1e-12f);
    __syncthreads();

    float* Cd = out + (size_t)b * CC * SS + n0;
#pragma unroll
    for (int mi = 0; mi < 4; mi++) {
        int r0 = wm + mi * 16 + (lane >> 2);
        float g0 = gamma2[r0], g1 = gamma2[r0 + 8];
#pragma unroll
        for (int ni = 0; ni < 4; ni++) {
            int cloc = wn + (ni >> 1) * 16 + (ni & 1) * 8 + (lane & 3) * 2;
            float s0 = csc[cloc], s1 = csc[cloc + 1];
            *(float2*)(Cd + (size_t)r0 * SS + cloc) =
                make_float2(acc[mi][ni][0] * s0 * g0, acc[mi][ni][1] * s1 * g0);
            *(float2*)(Cd + (size_t)(r0 + 8) * SS + cloc) =
                make_float2(acc[mi][ni][2] * s0 * g1, acc[mi][ni][3] * s1 * g1);
        }
    }
}

// ---------------------------------------------------------------------------
extern "C" void kernel_launch(void* const* d_in, const int* in_sizes, int n_in,
                              void* d_out, int out_size) {
    const float* x      = (const float*)d_in[0];
    const float* gamma1 = (const float*)d_in[1];
    const float* w_qkv  = (const float*)d_in[2];
    const float* w_out  = (const float*)d_in[3];
    const float* b_out  = (const float*)d_in[4];
    const float* gamma2 = (const float*)d_in[5];
    float* out = (float*)d_out;

    __half *woh_p, *mh_p;
    cudaGetSymbolAddress((void**)&woh_p, g_woh);
    cudaGetSymbolAddress((void**)&mh_p,  g_mh);

    const int SMEM_NT = (512 * 33 + 32) * 4;
    const int SMEM_G1 = NSTG * 49152;                  // 147456
    const int SMEM_CX = 65536;
    const int SMEM_G5 = NSTG * 36864 + 512;
    cudaFuncSetAttribute(k_normT,   cudaFuncAttributeMaxDynamicSharedMemorySize, SMEM_NT);
    cudaFuncSetAttribute(k_hgemm,   cudaFuncAttributeMaxDynamicSharedMemorySize, SMEM_G1);
    cudaFuncSetAttribute(k_ctx_mma, cudaFuncAttributeMaxDynamicSharedMemorySize, SMEM_CX);
    cudaFuncSetAttribute(k_ogemm,   cudaFuncAttributeMaxDynamicSharedMemorySize, SMEM_G5);

    k_prep_wq<<<QKV * CC / 256, 256>>>(w_qkv, gamma1);
    k_prep_wo<<<CC * CC / 256, 256>>>(w_out);
    k_normT<<<dim3(SS / 32, BB), 256, SMEM_NT>>>(x);
    // K1: qkv GEMM (128x256 tiles) + fused epilogues
    k_hgemm<<<dim3(SS / 256, QKV / 128, BB), 256, SMEM_G1>>>();
    // fold k row-sum partials
    k_ksumf<<<BB * 512 / 256, 256>>>();
    // ctx via tensor cores + finish
    k_ctx_mma<<<dim3(NSEG, HH, BB), 128, SMEM_CX>>>();
    k_ctx_fin<<<BB * HH * 4096 / 256, 256>>>();
    // apply exp(q) to ctx, normalize by qsum -> mh
    k_apply_mma<<<dim3(SS / 128, HH, BB), 256>>>();
    // K5: fused out-proj + bias + rms-norm
    k_ogemm<<<dim3(SS / 64, BB), 512, SMEM_G5>>>(woh_p, mh_p, out, b_out, gamma2);
}

// round 11
// speedup vs baseline: 1.0268x; 1.0268x over previous
#include <cuda_runtime.h>
#include <cuda_fp16.h>
#include <math.h>
#include <cstdint>

#define BB 16
#define CC 512
#define SS 4096
#define HH 8
#define DD 64
#define QKV 1536
#define NSTG 3
#define NSEG 16
#define CSEG 256

// ---------------- scratch (static __device__, allocation-free) ----------------
__device__ __half g_wqh[QKV * CC];
__device__ __half g_woh[CC * CC];
__device__ __half g_xh[(size_t)BB * SS * CC];          // 67 MB
__device__ __half g_qkvh[(size_t)BB * QKV * SS];       // v region used
__device__ __half g_ekh[(size_t)BB * 512 * SS];        // 67 MB  exp(k) fp16
__device__ float  g_ksump[128][BB * 512];              // 4 MB   k row-sum partials
__device__ float  g_ksum[BB * 512];
__device__ float  g_qsum[(size_t)BB * HH * SS];        // 2 MB   q col sums (per n)
__device__ float  g_ctxp[NSEG][BB * HH * DD * DD];
__device__ __half g_ctxh[BB * HH * DD * DD];
__device__ __half g_qs[(size_t)BB * HH * SS * DD];     // 67 MB  exp(q)^T [bh][n][d]
__device__ __half g_mh[(size_t)BB * SS * CC];          // 67 MB  midT fp16

// ---------------- helpers ----------------
__device__ __forceinline__ uint32_t smem_u32(const void* p) {
    uint32_t a;
    asm("{ .reg .u64 t; cvta.to.shared.u64 t, %1; cvt.u32.u64 %0, t; }" : "=r"(a) : "l"(p));
    return a;
}
#define CP_ASYNC(dst, src) \
    asm volatile("cp.async.cg.shared.global [%0], [%1], 16;" :: "r"(dst), "l"(src) : "memory")
#define CP_COMMIT() asm volatile("cp.async.commit_group;" ::: "memory")
#define CP_WAIT(n)  asm volatile("cp.async.wait_group %0;" :: "n"(n) : "memory")
#define LDSM4(R, addr) \
    asm volatile("ldmatrix.sync.aligned.m8n8.x4.shared.b16 {%0,%1,%2,%3}, [%4];" \
        : "=r"((R)[0]), "=r"((R)[1]), "=r"((R)[2]), "=r"((R)[3]) : "r"(addr))

__device__ __forceinline__ void mma16(float* c, const uint32_t* a, const uint32_t* b) {
    asm volatile(
        "mma.sync.aligned.m16n8k16.row.col.f32.f16.f16.f32 "
        "{%0,%1,%2,%3},{%4,%5,%6,%7},{%8,%9},{%0,%1,%2,%3};"
        : "+f"(c[0]), "+f"(c[1]), "+f"(c[2]), "+f"(c[3])
        : "r"(a[0]), "r"(a[1]), "r"(a[2]), "r"(a[3]), "r"(b[0]), "r"(b[1]));
}

// ---------------------------------------------------------------------------
// prep: both weight arrays -> fp16 scratch (gamma1 folded into w_qkv)
// ---------------------------------------------------------------------------
__global__ void k_prep(const float* __restrict__ wq, const float* __restrict__ g1,
                       const float* __restrict__ wo) {
    int i = blockIdx.x * 256 + threadIdx.x;
    if (i < QKV * CC) {
        g_wqh[i] = __float2half_rn(wq[i] * g1[i & (CC - 1)]);
    } else {
        int j = i - QKV * CC;
        g_woh[j] = __float2half_rn(wo[j]);
    }
}

// ---------------------------------------------------------------------------
// normT: xh[b][s][c] = fp16(x[b][c][s]*r[b,s])
// ---------------------------------------------------------------------------
__global__ void k_normT(const float* __restrict__ x) {
    extern __shared__ float sm[];
    float* tile = sm;                  // [512][33]
    float* rr = sm + 512 * 33;
    int b = blockIdx.y, s0 = blockIdx.x * 32;
    int t = threadIdx.x;
    const float* xp = x + (size_t)b * CC * SS + s0;

    for (int i = t; i < 512 * 32; i += 256) {
        int c = i >> 5, sl = i & 31;
        tile[c * 33 + sl] = xp[(size_t)c * SS + sl];
    }
    __syncthreads();

    int sl = t >> 3, part = t & 7;
    float acc = 0.f;
    for (int c = part; c < 512; c += 8) {
        float v = tile[c * 33 + sl];
        acc += v * v;
    }
#pragma unroll
    for (int o = 4; o; o >>= 1) acc += __shfl_down_sync(0xFFFFFFFFu, acc, o);
    if (part == 0) rr[sl] = 22.62741699796952f / fmaxf(sqrtf(acc), 1e-12f);
    __syncthreads();

    float rv = rr[sl];
    __half* op = g_xh + ((size_t)b * SS + s0 + sl) * CC;
    for (int c0 = part * 64; c0 < part * 64 + 64; c0 += 8) {
        __half h[8];
#pragma unroll
        for (int j = 0; j < 8; j++) h[j] = __float2half_rn(tile[(c0 + j) * 33 + sl] * rv);
        *(uint4*)(op + c0) = *(uint4*)h;
    }
}

// ---------------------------------------------------------------------------
// K1: qkv GEMM 128x128, BK=64, 3-stage, 8 warps 64x32, 2 CTA/SM.
// B-fragment double-buffered ks loop. Fused q/k/v epilogues.
// ---------------------------------------------------------------------------
__global__ __launch_bounds__(256, 2)
void k_hgemm() {
    extern __shared__ char smc[];
    uint32_t sbase = smem_u32(smc);

    int tid = threadIdx.x, lane = tid & 31, wid = tid >> 5;
    int b = blockIdx.z, m0 = blockIdx.y * 128, n0 = blockIdx.x * 128;
    const __half* Ab = g_wqh + (size_t)m0 * CC;
    const __half* Bb = g_xh + (size_t)b * SS * CC + (size_t)n0 * CC;

    const int NC = CC / 64;

    auto issue = [&](int kc, int buf) {
        const __half* Asrc = Ab + kc * 64;
        const __half* Bsrc = Bb + kc * 64;
        uint32_t base = sbase + buf * 32768;
#pragma unroll
        for (int it = 0; it < 4; it++) {
            int id = it * 256 + tid;
            int row = id >> 3, j = id & 7;
            uint32_t dst = base + row * 128 + ((j ^ (row & 7)) << 4);
            CP_ASYNC(dst, Asrc + (size_t)row * CC + j * 8);
            CP_ASYNC(dst + 16384, Bsrc + (size_t)row * CC + j * 8);
        }
    };

#pragma unroll
    for (int s = 0; s < NSTG - 1; s++) { issue(s, s); CP_COMMIT(); }

    int wm = (wid >> 2) * 64, wn = (wid & 3) * 32;
    int rA = wm + (lane & 7) + ((lane >> 3) & 1) * 8;
    int cA = (lane >> 4);
    int rB = wn + (lane & 7) + ((lane >> 4) & 1) * 8;
    int cB = (lane >> 3) & 1;
    int swA = rA & 7, swB = rB & 7;

    float acc[4][4][4] = {};

    for (int kc = 0; kc < NC; kc++) {
        CP_WAIT(NSTG - 2);
        __syncthreads();
        if (kc + NSTG - 1 < NC) issue(kc + NSTG - 1, (kc + NSTG - 1) % NSTG);
        CP_COMMIT();
        uint32_t bufA = sbase + (kc % NSTG) * 32768;
        uint32_t bufB = bufA + 16384;

        uint32_t bf[2][2][4];
        {
            uint32_t kchB = ((uint32_t)cB ^ swB) << 4;
#pragma unroll
            for (int p = 0; p < 2; p++)
                LDSM4(bf[0][p], bufB + (rB + p * 16) * 128 + kchB);
        }
#pragma unroll
        for (int ks = 0; ks < 4; ks++) {
            int cur = ks & 1;
            if (ks < 3) {
                uint32_t kchBn = ((uint32_t)((ks + 1) * 2 + cB) ^ swB) << 4;
#pragma unroll
                for (int p = 0; p < 2; p++)
                    LDSM4(bf[cur ^ 1][p], bufB + (rB + p * 16) * 128 + kchBn);
            }
            uint32_t a[4][4];
            uint32_t kchA = ((uint32_t)(ks * 2 + cA) ^ swA) << 4;
#pragma unroll
            for (int mi = 0; mi < 4; mi++)
                LDSM4(a[mi], bufA + (rA + mi * 16) * 128 + kchA);
#pragma unroll
            for (int mi = 0; mi < 4; mi++)
#pragma unroll
                for (int ni = 0; ni < 4; ni++)
                    mma16(acc[mi][ni], a[mi], bf[cur][ni >> 1] + (ni & 1) * 2);
        }
    }

    if (m0 < 512) {
        // ---- q: exp, transpose via smem, col sums ----
        __syncthreads();
        __half* qt = (__half*)smc;             // [c 0..127][r 0..127], stride 136
        float cs[8] = {};
#pragma unroll
        for (int mi = 0; mi < 4; mi++) {
#pragma unroll
            for (int ni = 0; ni < 4; ni++) {
                int c = wn + (ni >> 1) * 16 + (ni & 1) * 8 + (lane & 3) * 2;
                int r = wm + mi * 16 + (lane >> 2);
                float e0 = __expf(acc[mi][ni][0]);
                float e1 = __expf(acc[mi][ni][1]);
                float e2 = __expf(acc[mi][ni][2]);
                float e3 = __expf(acc[mi][ni][3]);
                qt[c * 136 + r]           = __float2half_rn(e0);
                qt[(c + 1) * 136 + r]     = __float2half_rn(e1);
                qt[c * 136 + r + 8]       = __float2half_rn(e2);
                qt[(c + 1) * 136 + r + 8] = __float2half_rn(e3);
                cs[ni * 2]     += e0 + e2;
                cs[ni * 2 + 1] += e1 + e3;
            }
        }
#pragma unroll
        for (int j = 0; j < 8; j++)
#pragma unroll
            for (int o = 4; o <= 16; o <<= 1)
                cs[j] += __shfl_xor_sync(0xFFFFFFFFu, cs[j], o);
        int head = (m0 >> 6) + (wid >> 2);
        if ((lane >> 2) == 0) {
            float* qsump = g_qsum + (size_t)(b * HH + head) * SS + n0;
#pragma unroll
            for (int j = 0; j < 8; j++) {
                int c = wn + ((j >> 2) ? 16 : 0) + (((j >> 1) & 1) ? 8 : 0) +
                        (lane & 3) * 2 + (j & 1);
                qsump[c] = cs[j];
            }
        }
        __syncthreads();
        int n = tid >> 1, hh = tid & 1;
        const uint4* src = (const uint4*)(qt + n * 136 + hh * 64);
        __half* dst = g_qs + ((size_t)(b * HH + (m0 >> 6) + hh) * SS + n0 + n) * 64;
#pragma unroll
        for (int j = 0; j < 8; j++) ((uint4*)dst)[j] = src[j];
    } else if (m0 < 1024) {
        // ---- k: exp store + row-sum partials ----
        float rs[8] = {};
        __half* ekd = g_ekh + (size_t)(b * 512 + m0 - 512) * SS + n0;
#pragma unroll
        for (int mi = 0; mi < 4; mi++) {
            int r = wm + mi * 16 + (lane >> 2);
#pragma unroll
            for (int ni = 0; ni < 4; ni++) {
                int c = wn + (ni >> 1) * 16 + (ni & 1) * 8 + (lane & 3) * 2;
                float e0 = __expf(acc[mi][ni][0]);
                float e1 = __expf(acc[mi][ni][1]);
                float e2 = __expf(acc[mi][ni][2]);
                float e3 = __expf(acc[mi][ni][3]);
                *(__half2*)(ekd + (size_t)r * SS + c) = __floats2half2_rn(e0, e1);
                *(__half2*)(ekd + (size_t)(r + 8) * SS + c) = __floats2half2_rn(e2, e3);
                rs[mi * 2]     += e0 + e1;
                rs[mi * 2 + 1] += e2 + e3;
            }
        }
#pragma unroll
        for (int j = 0; j < 8; j++) {
            rs[j] += __shfl_xor_sync(0xFFFFFFFFu, rs[j], 1);
            rs[j] += __shfl_xor_sync(0xFFFFFFFFu, rs[j], 2);
        }
        if ((lane & 3) == 0) {
            int slot = blockIdx.x * 4 + (wid & 3);
            float* kp = g_ksump[slot] + b * 512 + (m0 - 512) + wm;
#pragma unroll
            for (int j = 0; j < 8; j++)
                kp[(j >> 1) * 16 + (lane >> 2) + (j & 1) * 8] = rs[j];
        }
    } else {
        // ---- v: plain fp16 ----
        __half* Cd = g_qkvh + (size_t)b * QKV * SS;
#pragma unroll
        for (int mi = 0; mi < 4; mi++) {
            int r0 = m0 + wm + mi * 16 + (lane >> 2);
#pragma unroll
            for (int ni = 0; ni < 4; ni++) {
                int c = n0 + wn + (ni >> 1) * 16 + (ni & 1) * 8 + (lane & 3) * 2;
                *(__half2*)(Cd + (size_t)r0 * SS + c) =
                    __floats2half2_rn(acc[mi][ni][0], acc[mi][ni][1]);
                *(__half2*)(Cd + (size_t)(r0 + 8) * SS + c) =
                    __floats2half2_rn(acc[mi][ni][2], acc[mi][ni][3]);
            }
        }
    }
}

// ---------------------------------------------------------------------------
// ksum finish: sum the 128 partial slots
// ---------------------------------------------------------------------------
__global__ void k_ksumf() {
    int i = blockIdx.x * 256 + threadIdx.x;        // 8192
    float s = 0.f;
#pragma unroll 8
    for (int t = 0; t < 128; t++) s += g_ksump[t][i];
    g_ksum[i] = s;
}

// ---------------------------------------------------------------------------
// ctx_mma: partial ctxT[e][d] = sum_{n in seg} v[e,n] * ek[d,n]
// ---------------------------------------------------------------------------
__global__ __launch_bounds__(128, 3)
void k_ctx_mma() {
    extern __shared__ char smc[];
    int seg = blockIdx.x, h = blockIdx.y, b = blockIdx.z;
    int n0 = seg * CSEG;
    const __half* vp = g_qkvh + ((size_t)b * QKV + 1024 + h * 64) * SS + n0;
    const __half* ekp = g_ekh + (size_t)(b * 512 + h * 64) * SS + n0;

    uint32_t sA = smem_u32(smc), sB = sA + 32768;
    int tid = threadIdx.x, lane = tid & 31, wid = tid >> 5;

#pragma unroll
    for (int it = 0; it < 16; it++) {
        int id = it * 128 + tid;
        int row = id >> 5, j = id & 31;
        uint32_t soff = row * 512 + (((uint32_t)(j ^ (row & 7))) << 4);
        CP_ASYNC(sA + soff, vp + (size_t)row * SS + j * 8);
        CP_ASYNC(sB + soff, ekp + (size_t)row * SS + j * 8);
    }
    CP_COMMIT();
    CP_WAIT(0);
    __syncthreads();

    int rA = wid * 16 + (lane & 7) + ((lane >> 3) & 1) * 8;
    int cA = lane >> 4;
    int rB = (lane & 7) + ((lane >> 4) & 1) * 8;
    int cB = (lane >> 3) & 1;
    int swA = rA & 7, swB = rB & 7;

    float acc[8][4] = {};
#pragma unroll
    for (int ks = 0; ks < 16; ks++) {
        uint32_t a[4], bf[4][4];
        LDSM4(a, sA + rA * 512 + (((uint32_t)(ks * 2 + cA) ^ swA) << 4));
#pragma unroll
        for (int p = 0; p < 4; p++)
            LDSM4(bf[p], sB + (rB + p * 16) * 512 + (((uint32_t)(ks * 2 + cB) ^ swB) << 4));
#pragma unroll
        for (int p = 0; p < 4; p++)
#pragma unroll
            for (int hf = 0; hf < 2; hf++)
                mma16(acc[p * 2 + hf], a, bf[p] + hf * 2);
    }

    float* cp = g_ctxp[seg] + (size_t)(b * HH + h) * 4096;
    int r0 = wid * 16 + (lane >> 2);
#pragma unroll
    for (int ni = 0; ni < 8; ni++) {
        int d = (ni >> 1) * 16 + (ni & 1) * 8 + (lane & 3) * 2;
        *(float2*)(cp + r0 * 64 + d) = make_float2(acc[ni][0], acc[ni][1]);
        *(float2*)(cp + (r0 + 8) * 64 + d) = make_float2(acc[ni][2], acc[ni][3]);
    }
}

// ---------------------------------------------------------------------------
// ctx finish: ctxh[bh][e][d] = fp16( 0.125/ksum[d] * sum_seg ctxp )
// ---------------------------------------------------------------------------
__global__ void k_ctx_fin() {
    int i = blockIdx.x * 256 + threadIdx.x;
    int bh = i >> 12, d = i & 63;
    float s = 0.f;
#pragma unroll
    for (int p = 0; p < NSEG; p++) s += g_ctxp[p][i];
    float inv = 0.125f / g_ksum[(bh >> 3) * 512 + (bh & 7) * 64 + d];
    g_ctxh[i] = __float2half_rn(s * inv);
}

// ---------------------------------------------------------------------------
// apply_mma: mh[b][n][h*64+e] = (1/qsum[n]) * sum_d eq[bh][n][d] * ctxh[bh][e][d]
// ---------------------------------------------------------------------------
__global__ __launch_bounds__(256, 2)
void k_apply_mma() {
    __shared__ __align__(16) char smc[24576];
    int nt = blockIdx.x, h = blockIdx.y, b = blockIdx.z;
    int n0 = nt * 128;
    const __half* Aq = g_qs + ((size_t)(b * HH + h) * SS + n0) * 64;
    const __half* Bc = g_ctxh + (size_t)(b * HH + h) * 4096;
    const float* qsp = g_qsum + (size_t)(b * HH + h) * SS + n0;

    uint32_t sA = smem_u32(smc), sB = sA + 16384;
    int tid = threadIdx.x, lane = tid & 31, wid = tid >> 5;

#pragma unroll
    for (int it = 0; it < 4; it++) {
        int id = it * 256 + tid;
        int row = id >> 3, j = id & 7;
        CP_ASYNC(sA + row * 128 + ((uint32_t)(j ^ (row & 7)) << 4),
                 Aq + (size_t)row * 64 + j * 8);
    }
#pragma unroll
    for (int it = 0; it < 2; it++) {
        int id = it * 256 + tid;
        int row = id >> 3, j = id & 7;
        CP_ASYNC(sB + row * 128 + ((uint32_t)(j ^ (row & 7)) << 4),
                 Bc + (size_t)row * 64 + j * 8);
    }
    CP_COMMIT();
    CP_WAIT(0);
    __syncthreads();

    int wm = (wid >> 1) * 32, wn = (wid & 1) * 32;
    int rA = wm + (lane & 7) + ((lane >> 3) & 1) * 8;
    int cA = lane >> 4;
    int rB = wn + (lane & 7) + ((lane >> 4) & 1) * 8;
    int cB = (lane >> 3) & 1;
    int swA = rA & 7, swB = rB & 7;

    float acc[2][4][4] = {};
#pragma unroll
    for (int ks = 0; ks < 4; ks++) {
        uint32_t a[2][4], bf[2][4];
        uint32_t kchA = ((uint32_t)(ks * 2 + cA) ^ swA) << 4;
        uint32_t kchB = ((uint32_t)(ks * 2 + cB) ^ swB) << 4;
#pragma unroll
        for (int mi = 0; mi < 2; mi++)
            LDSM4(a[mi], sA + (rA + mi * 16) * 128 + kchA);
#pragma unroll
        for (int p = 0; p < 2; p++)
            LDSM4(bf[p], sB + (rB + p * 16) * 128 + kchB);
#pragma unroll
        for (int mi = 0; mi < 2; mi++)
#pragma unroll
            for (int ni = 0; ni < 4; ni++)
                mma16(acc[mi][ni], a[mi], bf[ni >> 1] + (ni & 1) * 2);
    }

    __half* outp = g_mh + (size_t)b * SS * CC;
#pragma unroll
    for (int mi = 0; mi < 2; mi++) {
        int rl = wm + mi * 16 + (lane >> 2);
        float i0 = 1.f / qsp[rl];
        float i1 = 1.f / qsp[rl + 8];
        int r = n0 + rl;
#pragma unroll
        for (int ni = 0; ni < 4; ni++) {
            int c = h * 64 + wn + (ni >> 1) * 16 + (ni & 1) * 8 + (lane & 3) * 2;
            *(__half2*)(outp + (size_t)r * CC + c) =
                __floats2half2_rn(acc[mi][ni][0] * i0, acc[mi][ni][1] * i0);
            *(__half2*)(outp + (size_t)(r + 8) * CC + c) =
                __floats2half2_rn(acc[mi][ni][2] * i1, acc[mi][ni][3] * i1);
        }
    }
}

// ---------------------------------------------------------------------------
// K5: out = rmsnorm( wo @ mh^T + bias ) * gamma2
// ---------------------------------------------------------------------------
__global__ __launch_bounds__(512, 1)
void k_ogemm(const __half* __restrict__ A, const __half* __restrict__ Bg,
             float* __restrict__ out, const float* __restrict__ bias,
             const float* __restrict__ gamma2) {
    extern __shared__ char smc[];
    const int STG = 36864;
    uint32_t sbase = smem_u32(smc);
    float* colsq = (float*)(smc + 3 * STG);
    float* csc   = colsq + 64;

    int tid = threadIdx.x, lane = tid & 31, wid = tid >> 5;
    int b = blockIdx.y, n0 = blockIdx.x * 64;
    const __half* Bb = Bg + ((size_t)b * SS + n0) * CC;

    if (tid < 64) colsq[tid] = 0.f;

    auto issue = [&](int kc, int buf) {
        uint32_t base = sbase + buf * STG;
#pragma unroll
        for (int it = 0; it < 4; it++) {
            int id = it * 512 + tid;
            int row = id >> 2, j = id & 3;
            uint32_t dst = base + row * 64 + (((uint32_t)j ^ ((row >> 1) & 3)) << 4);
            CP_ASYNC(dst, A + (size_t)row * CC + kc * 32 + j * 8);
        }
        if (tid < 256) {
            int row = tid >> 2, j = tid & 3;
            uint32_t dst = base + 32768 + row * 64 + (((uint32_t)j ^ ((row >> 1) & 3)) << 4);
            CP_ASYNC(dst, Bb + (size_t)row * CC + kc * 32 + j * 8);
        }
    };

#pragma unroll
    for (int s = 0; s < NSTG - 1; s++) { issue(s, s); CP_COMMIT(); }

    int wm = (wid >> 1) * 64, wn = (wid & 1) * 32;
    int rA = wm + (lane & 7) + ((lane >> 3) & 1) * 8;
    int cA = (lane >> 4);
    int rB = wn + (lane & 7) + ((lane >> 4) & 1) * 8;
    int cB = (lane >> 3) & 1;
    int swA = (rA >> 1) & 3, swB = (rB >> 1) & 3;

    float acc[4][4][4] = {};
    const int NC = CC / 32;

    for (int kc = 0; kc < NC; kc++) {
        CP_WAIT(NSTG - 2);
        __syncthreads();
        if (kc + NSTG - 1 < NC) issue(kc + NSTG - 1, (kc + NSTG - 1) % NSTG);
        CP_COMMIT();
        uint32_t bufA = sbase + (kc % NSTG) * STG;
        uint32_t bufB = bufA + 32768;
#pragma unroll
        for (int ks = 0; ks < 2; ks++) {
            uint32_t a[4][4], bf[2][4];
            uint32_t kchA = ((uint32_t)(ks * 2 + cA) ^ swA) << 4;
            uint32_t kchB = ((uint32_t)(ks * 2 + cB) ^ swB) << 4;
#pragma unroll
            for (int mi = 0; mi < 4; mi++)
                LDSM4(a[mi], bufA + (rA + mi * 16) * 64 + kchA);
#pragma unroll
            for (int p = 0; p < 2; p++)
                LDSM4(bf[p], bufB + (rB + p * 16) * 64 + kchB);
#pragma unroll
            for (int mi = 0; mi < 4; mi++)
#pragma unroll
                for (int ni = 0; ni < 4; ni++)
                    mma16(acc[mi][ni], a[mi], bf[ni >> 1] + (ni & 1) * 2);
        }
    }

    float bi0[4], bi1[4];
#pragma unroll
    for (int mi = 0; mi < 4; mi++) {
        bi0[mi] = bias[wm + mi * 16 + (lane >> 2)];
        bi1[mi] = bias[wm + mi * 16 + (lane >> 2) + 8];
    }
#pragma unroll
    for (int ni = 0; ni < 4; ni++) {
        float l0 = 0.f, l1 = 0.f;
#pragma unroll
        for (int mi = 0; mi < 4; mi++) {
            acc[mi][ni][0] += bi0[mi]; acc[mi][ni][1] += bi0[mi];
            acc[mi][ni][2] += bi1[mi]; acc[mi][ni][3] += bi1[mi];
            l0 += acc[mi][ni][0] * acc[mi][ni][0] + acc[mi][ni][2] * acc[mi][ni][2];
            l1 += acc[mi][ni][1] * acc[mi][ni][1] + acc[mi][ni][3] * acc[mi][ni][3];
        }
#pragma unroll
        for (int o = 4; o <= 16; o <<= 1) {
            l0 += __shfl_xor_sync(0xFFFFFFFFu, l0, o);
            l1 += __shfl_xor_sync(0xFFFFFFFFu, l1, o);
        }
        if ((lane >> 2) == 0) {
            int cloc = wn + (ni >> 1) * 16 + (ni & 1) * 8 + (lane & 3) * 2;
            atomicAdd(colsq + cloc, l0);
            atomicAdd(colsq + cloc + 1, l1);
        }
    }
    __syncthreads();
    if (tid < 64)
        csc[tid] = 22.62741699796952f / fmaxf(sqrtf(colsq[tid]), 1e-12f);
    __syncthreads();

    float* Cd = out + (size_t)b * CC * SS + n0;
#pragma unroll
    for (int mi = 0; mi < 4; mi++) {
        int r0 = wm + mi * 16 + (lane >> 2);
        float g0 = gamma2[r0], g1 = gamma2[r0 + 8];
#pragma unroll
        for (int ni = 0; ni < 4; ni++) {
            int cloc = wn + (ni >> 1) * 16 + (ni & 1) * 8 + (lane & 3) * 2;
            float s0 = csc[cloc], s1 = csc[cloc + 1];
            *(float2*)(Cd + (size_t)r0 * SS + cloc) =
                make_float2(acc[mi][ni][0] * s0 * g0, acc[mi][ni][1] * s1 * g0);
            *(float2*)(Cd + (size_t)(r0 + 8) * SS + cloc) =
                make_float2(acc[mi][ni][2] * s0 * g1, acc[mi][ni][3] * s1 * g1);
        }
    }
}

// ---------------------------------------------------------------------------
extern "C" void kernel_launch(void* const* d_in, const int* in_sizes, int n_in,
                              void* d_out, int out_size) {
    const float* x      = (const float*)d_in[0];
    const float* gamma1 = (const float*)d_in[1];
    const float* w_qkv  = (const float*)d_in[2];
    const float* w_out  = (const float*)d_in[3];
    const float* b_out  = (const float*)d_in[4];
    const float* gamma2 = (const float*)d_in[5];
    float* out = (float*)d_out;

    __half *woh_p, *mh_p;
    cudaGetSymbolAddress((void**)&woh_p, g_woh);
    cudaGetSymbolAddress((void**)&mh_p,  g_mh);

    const int SMEM_NT = (512 * 33 + 32) * 4;
    const int SMEM_G1 = NSTG * 32768;
    const int SMEM_CX = 65536;
    const int SMEM_G5 = NSTG * 36864 + 512;
    cudaFuncSetAttribute(k_normT,   cudaFuncAttributeMaxDynamicSharedMemorySize, SMEM_NT);
    cudaFuncSetAttribute(k_hgemm,   cudaFuncAttributeMaxDynamicSharedMemorySize, SMEM_G1);
    cudaFuncSetAttribute(k_ctx_mma, cudaFuncAttributeMaxDynamicSharedMemorySize, SMEM_CX);
    cudaFuncSetAttribute(k_ogemm,   cudaFuncAttributeMaxDynamicSharedMemorySize, SMEM_G5);

    k_prep<<<(QKV * CC + CC * CC) / 256, 256>>>(w_qkv, gamma1, w_out);
    k_normT<<<dim3(SS / 32, BB), 256, SMEM_NT>>>(x);
    // K1: qkv GEMM (128x128) + fused epilogues
    k_hgemm<<<dim3(SS / 128, QKV / 128, BB), 256, SMEM_G1>>>();
    // fold k row-sum partials
    k_ksumf<<<BB * 512 / 256, 256>>>();
    // ctx via tensor cores + finish
    k_ctx_mma<<<dim3(NSEG, HH, BB), 128, SMEM_CX>>>();
    k_ctx_fin<<<BB * HH * 4096 / 256, 256>>>();
    // apply exp(q) to ctx, normalize by qsum -> mh
    k_apply_mma<<<dim3(SS / 128, HH, BB), 256>>>();
    // K5: fused out-proj + bias + rms-norm
    k_ogemm<<<dim3(SS / 64, BB), 512, SMEM_G5>>>(woh_p, mh_p, out, b_out, gamma2);
}

// round 12
// speedup vs baseline: 1.0561x; 1.0285x over previous
#include <cuda_runtime.h>
#include <cuda_fp16.h>
#include <math.h>
#include <cstdint>

#define BB 16
#define CC 512
#define SS 4096
#define HH 8
#define DD 64
#define QKV 1536
#define NSTG 3
#define NSEG 8
#define CSEG 512

// ---------------- scratch (static __device__, allocation-free) ----------------
__device__ __half g_wqh[QKV * CC];
__device__ __half g_woh[CC * CC];
__device__ __half g_xh[(size_t)BB * SS * CC];          // 67 MB
__device__ __half g_qkvh[(size_t)BB * QKV * SS];       // v region used
__device__ __half g_ekh[(size_t)BB * 512 * SS];        // 67 MB  exp(k) fp16
__device__ float  g_ksump[128][BB * 512];              // 4 MB   k row-sum partials
__device__ float  g_ksum[BB * 512];
__device__ float  g_qsum[(size_t)BB * HH * SS];        // 2 MB   q col sums (per n)
__device__ float  g_ctxp[NSEG][BB * HH * DD * DD];
__device__ __half g_ctxh[BB * HH * DD * DD];
__device__ __half g_qs[(size_t)BB * HH * SS * DD];     // 67 MB  exp(q)^T [bh][n][d]
__device__ __half g_mh[(size_t)BB * SS * CC];          // 67 MB  midT fp16

// ---------------- helpers ----------------
__device__ __forceinline__ uint32_t smem_u32(const void* p) {
    uint32_t a;
    asm("{ .reg .u64 t; cvta.to.shared.u64 t, %1; cvt.u32.u64 %0, t; }" : "=r"(a) : "l"(p));
    return a;
}
#define CP_ASYNC(dst, src) \
    asm volatile("cp.async.cg.shared.global [%0], [%1], 16;" :: "r"(dst), "l"(src) : "memory")
#define CP_COMMIT() asm volatile("cp.async.commit_group;" ::: "memory")
#define CP_WAIT(n)  asm volatile("cp.async.wait_group %0;" :: "n"(n) : "memory")
#define LDSM4(R, addr) \
    asm volatile("ldmatrix.sync.aligned.m8n8.x4.shared.b16 {%0,%1,%2,%3}, [%4];" \
        : "=r"((R)[0]), "=r"((R)[1]), "=r"((R)[2]), "=r"((R)[3]) : "r"(addr))

__device__ __forceinline__ void mma16(float* c, const uint32_t* a, const uint32_t* b) {
    asm volatile(
        "mma.sync.aligned.m16n8k16.row.col.f32.f16.f16.f32 "
        "{%0,%1,%2,%3},{%4,%5,%6,%7},{%8,%9},{%0,%1,%2,%3};"
        : "+f"(c[0]), "+f"(c[1]), "+f"(c[2]), "+f"(c[3])
        : "r"(a[0]), "r"(a[1]), "r"(a[2]), "r"(a[3]), "r"(b[0]), "r"(b[1]));
}

// ---------------------------------------------------------------------------
// prep: both weight arrays -> fp16 scratch (gamma1 folded into w_qkv)
// ---------------------------------------------------------------------------
__global__ void k_prep(const float* __restrict__ wq, const float* __restrict__ g1,
                       const float* __restrict__ wo) {
    int i = blockIdx.x * 256 + threadIdx.x;
    if (i < QKV * CC) {
        g_wqh[i] = __float2half_rn(wq[i] * g1[i & (CC - 1)]);
    } else {
        int j = i - QKV * CC;
        g_woh[j] = __float2half_rn(wo[j]);
    }
}

// ---------------------------------------------------------------------------
// normT: xh[b][s][c] = fp16(x[b][c][s]*r[b,s])
// ---------------------------------------------------------------------------
__global__ void k_normT(const float* __restrict__ x) {
    extern __shared__ float sm[];
    float* tile = sm;                  // [512][33]
    float* rr = sm + 512 * 33;
    int b = blockIdx.y, s0 = blockIdx.x * 32;
    int t = threadIdx.x;
    const float* xp = x + (size_t)b * CC * SS + s0;

    for (int i = t; i < 512 * 32; i += 256) {
        int c = i >> 5, sl = i & 31;
        tile[c * 33 + sl] = xp[(size_t)c * SS + sl];
    }
    __syncthreads();

    int sl = t >> 3, part = t & 7;
    float acc = 0.f;
    for (int c = part; c < 512; c += 8) {
        float v = tile[c * 33 + sl];
        acc += v * v;
    }
#pragma unroll
    for (int o = 4; o; o >>= 1) acc += __shfl_down_sync(0xFFFFFFFFu, acc, o);
    if (part == 0) rr[sl] = 22.62741699796952f / fmaxf(sqrtf(acc), 1e-12f);
    __syncthreads();

    float rv = rr[sl];
    __half* op = g_xh + ((size_t)b * SS + s0 + sl) * CC;
    for (int c0 = part * 64; c0 < part * 64 + 64; c0 += 8) {
        __half h[8];
#pragma unroll
        for (int j = 0; j < 8; j++) h[j] = __float2half_rn(tile[(c0 + j) * 33 + sl] * rv);
        *(uint4*)(op + c0) = *(uint4*)h;
    }
}

// ---------------------------------------------------------------------------
// K1: qkv GEMM 128x128, BK=64, 3-stage, 8 warps 64x32, 2 CTA/SM.
// Fused q/k/v epilogues.
// ---------------------------------------------------------------------------
__global__ __launch_bounds__(256, 2)
void k_hgemm() {
    extern __shared__ char smc[];
    uint32_t sbase = smem_u32(smc);

    int tid = threadIdx.x, lane = tid & 31, wid = tid >> 5;
    int b = blockIdx.z, m0 = blockIdx.y * 128, n0 = blockIdx.x * 128;
    const __half* Ab = g_wqh + (size_t)m0 * CC;
    const __half* Bb = g_xh + (size_t)b * SS * CC + (size_t)n0 * CC;

    const int NC = CC / 64;

    auto issue = [&](int kc, int buf) {
        const __half* Asrc = Ab + kc * 64;
        const __half* Bsrc = Bb + kc * 64;
        uint32_t base = sbase + buf * 32768;
#pragma unroll
        for (int it = 0; it < 4; it++) {
            int id = it * 256 + tid;
            int row = id >> 3, j = id & 7;
            uint32_t dst = base + row * 128 + ((j ^ (row & 7)) << 4);
            CP_ASYNC(dst, Asrc + (size_t)row * CC + j * 8);
            CP_ASYNC(dst + 16384, Bsrc + (size_t)row * CC + j * 8);
        }
    };

#pragma unroll
    for (int s = 0; s < NSTG - 1; s++) { issue(s, s); CP_COMMIT(); }

    int wm = (wid >> 2) * 64, wn = (wid & 3) * 32;
    int rA = wm + (lane & 7) + ((lane >> 3) & 1) * 8;
    int cA = (lane >> 4);
    int rB = wn + (lane & 7) + ((lane >> 4) & 1) * 8;
    int cB = (lane >> 3) & 1;
    int swA = rA & 7, swB = rB & 7;

    float acc[4][4][4] = {};

    for (int kc = 0; kc < NC; kc++) {
        CP_WAIT(NSTG - 2);
        __syncthreads();
        if (kc + NSTG - 1 < NC) issue(kc + NSTG - 1, (kc + NSTG - 1) % NSTG);
        CP_COMMIT();
        uint32_t bufA = sbase + (kc % NSTG) * 32768;
        uint32_t bufB = bufA + 16384;
#pragma unroll
        for (int ks = 0; ks < 4; ks++) {
            uint32_t a[4][4], bf[2][4];
            uint32_t kchA = ((uint32_t)(ks * 2 + cA) ^ swA) << 4;
            uint32_t kchB = ((uint32_t)(ks * 2 + cB) ^ swB) << 4;
#pragma unroll
            for (int mi = 0; mi < 4; mi++)
                LDSM4(a[mi], bufA + (rA + mi * 16) * 128 + kchA);
#pragma unroll
            for (int p = 0; p < 2; p++)
                LDSM4(bf[p], bufB + (rB + p * 16) * 128 + kchB);
#pragma unroll
            for (int mi = 0; mi < 4; mi++)
#pragma unroll
                for (int ni = 0; ni < 4; ni++)
                    mma16(acc[mi][ni], a[mi], bf[ni >> 1] + (ni & 1) * 2);
        }
    }

    if (m0 < 512) {
        // ---- q: exp, transpose via smem, col sums ----
        __syncthreads();
        __half* qt = (__half*)smc;             // [c 0..127][r 0..127], stride 136
        float cs[8] = {};
#pragma unroll
        for (int mi = 0; mi < 4; mi++) {
#pragma unroll
            for (int ni = 0; ni < 4; ni++) {
                int c = wn + (ni >> 1) * 16 + (ni & 1) * 8 + (lane & 3) * 2;
                int r = wm + mi * 16 + (lane >> 2);
                float e0 = __expf(acc[mi][ni][0]);
                float e1 = __expf(acc[mi][ni][1]);
                float e2 = __expf(acc[mi][ni][2]);
                float e3 = __expf(acc[mi][ni][3]);
                qt[c * 136 + r]           = __float2half_rn(e0);
                qt[(c + 1) * 136 + r]     = __float2half_rn(e1);
                qt[c * 136 + r + 8]       = __float2half_rn(e2);
                qt[(c + 1) * 136 + r + 8] = __float2half_rn(e3);
                cs[ni * 2]     += e0 + e2;
                cs[ni * 2 + 1] += e1 + e3;
            }
        }
#pragma unroll
        for (int j = 0; j < 8; j++)
#pragma unroll
            for (int o = 4; o <= 16; o <<= 1)
                cs[j] += __shfl_xor_sync(0xFFFFFFFFu, cs[j], o);
        int head = (m0 >> 6) + (wid >> 2);
        if ((lane >> 2) == 0) {
            float* qsump = g_qsum + (size_t)(b * HH + head) * SS + n0;
#pragma unroll
            for (int j = 0; j < 8; j++) {
                int c = wn + ((j >> 2) ? 16 : 0) + (((j >> 1) & 1) ? 8 : 0) +
                        (lane & 3) * 2 + (j & 1);
                qsump[c] = cs[j];
            }
        }
        __syncthreads();
        int n = tid >> 1, hh = tid & 1;
        const uint4* src = (const uint4*)(qt + n * 136 + hh * 64);
        __half* dst = g_qs + ((size_t)(b * HH + (m0 >> 6) + hh) * SS + n0 + n) * 64;
#pragma unroll
        for (int j = 0; j < 8; j++) ((uint4*)dst)[j] = src[j];
    } else if (m0 < 1024) {
        // ---- k: exp store + row-sum partials ----
        float rs[8] = {};
        __half* ekd = g_ekh + (size_t)(b * 512 + m0 - 512) * SS + n0;
#pragma unroll
        for (int mi = 0; mi < 4; mi++) {
            int r = wm + mi * 16 + (lane >> 2);
#pragma unroll
            for (int ni = 0; ni < 4; ni++) {
                int c = wn + (ni >> 1) * 16 + (ni & 1) * 8 + (lane & 3) * 2;
                float e0 = __expf(acc[mi][ni][0]);
                float e1 = __expf(acc[mi][ni][1]);
                float e2 = __expf(acc[mi][ni][2]);
                float e3 = __expf(acc[mi][ni][3]);
                *(__half2*)(ekd + (size_t)r * SS + c) = __floats2half2_rn(e0, e1);
                *(__half2*)(ekd + (size_t)(r + 8) * SS + c) = __floats2half2_rn(e2, e3);
                rs[mi * 2]     += e0 + e1;
                rs[mi * 2 + 1] += e2 + e3;
            }
        }
#pragma unroll
        for (int j = 0; j < 8; j++) {
            rs[j] += __shfl_xor_sync(0xFFFFFFFFu, rs[j], 1);
            rs[j] += __shfl_xor_sync(0xFFFFFFFFu, rs[j], 2);
        }
        if ((lane & 3) == 0) {
            int slot = blockIdx.x * 4 + (wid & 3);
            float* kp = g_ksump[slot] + b * 512 + (m0 - 512) + wm;
#pragma unroll
            for (int j = 0; j < 8; j++)
                kp[(j >> 1) * 16 + (lane >> 2) + (j & 1) * 8] = rs[j];
        }
    } else {
        // ---- v: plain fp16 ----
        __half* Cd = g_qkvh + (size_t)b * QKV * SS;
#pragma unroll
        for (int mi = 0; mi < 4; mi++) {
            int r0 = m0 + wm + mi * 16 + (lane >> 2);
#pragma unroll
            for (int ni = 0; ni < 4; ni++) {
                int c = n0 + wn + (ni >> 1) * 16 + (ni & 1) * 8 + (lane & 3) * 2;
                *(__half2*)(Cd + (size_t)r0 * SS + c) =
                    __floats2half2_rn(acc[mi][ni][0], acc[mi][ni][1]);
                *(__half2*)(Cd + (size_t)(r0 + 8) * SS + c) =
                    __floats2half2_rn(acc[mi][ni][2], acc[mi][ni][3]);
            }
        }
    }
}

// ---------------------------------------------------------------------------
// ksum finish: parallel fold of 128 slots (8 threads per output, shfl tree)
// ---------------------------------------------------------------------------
__global__ void k_ksumf() {
    int g = blockIdx.x * 256 + threadIdx.x;        // 65536 threads
    int i = g >> 3, sub = g & 7;
    float s = 0.f;
#pragma unroll
    for (int t = 0; t < 16; t++) s += g_ksump[sub * 16 + t][i];
#pragma unroll
    for (int o = 4; o; o >>= 1) s += __shfl_down_sync(0xFFFFFFFFu, s, o);
    if (sub == 0) g_ksum[i] = s;
}

// ---------------------------------------------------------------------------
// ctx_mma: partial ctxT[e][d] = sum_{n in seg(512)} v[e,n] * ek[d,n]
// grid (NSEG=8, HH, BB); inner loop over 2 x 256-column chunks, smem 64KB.
// ---------------------------------------------------------------------------
__global__ __launch_bounds__(128, 3)
void k_ctx_mma() {
    extern __shared__ char smc[];
    int seg = blockIdx.x, h = blockIdx.y, b = blockIdx.z;
    const __half* vbase = g_qkvh + ((size_t)b * QKV + 1024 + h * 64) * SS;
    const __half* ebase = g_ekh + (size_t)(b * 512 + h * 64) * SS;

    uint32_t sA = smem_u32(smc), sB = sA + 32768;
    int tid = threadIdx.x, lane = tid & 31, wid = tid >> 5;

    int rA = wid * 16 + (lane & 7) + ((lane >> 3) & 1) * 8;
    int cA = lane >> 4;
    int rB = (lane & 7) + ((lane >> 4) & 1) * 8;
    int cB = (lane >> 3) & 1;
    int swA = rA & 7, swB = rB & 7;

    float acc[8][4] = {};

    for (int c2 = 0; c2 < 2; c2++) {
        int n0 = seg * CSEG + c2 * 256;
        const __half* vp = vbase + n0;
        const __half* ekp = ebase + n0;
        if (c2) __syncthreads();               // protect smem reuse
#pragma unroll
        for (int it = 0; it < 16; it++) {
            int id = it * 128 + tid;
            int row = id >> 5, j = id & 31;
            uint32_t soff = row * 512 + (((uint32_t)(j ^ (row & 7))) << 4);
            CP_ASYNC(sA + soff, vp + (size_t)row * SS + j * 8);
            CP_ASYNC(sB + soff, ekp + (size_t)row * SS + j * 8);
        }
        CP_COMMIT();
        CP_WAIT(0);
        __syncthreads();

#pragma unroll
        for (int ks = 0; ks < 16; ks++) {
            uint32_t a[4], bf[4][4];
            LDSM4(a, sA + rA * 512 + (((uint32_t)(ks * 2 + cA) ^ swA) << 4));
#pragma unroll
            for (int p = 0; p < 4; p++)
                LDSM4(bf[p], sB + (rB + p * 16) * 512 + (((uint32_t)(ks * 2 + cB) ^ swB) << 4));
#pragma unroll
            for (int p = 0; p < 4; p++)
#pragma unroll
                for (int hf = 0; hf < 2; hf++)
                    mma16(acc[p * 2 + hf], a, bf[p] + hf * 2);
        }
    }

    float* cp = g_ctxp[seg] + (size_t)(b * HH + h) * 4096;
    int r0 = wid * 16 + (lane >> 2);
#pragma unroll
    for (int ni = 0; ni < 8; ni++) {
        int d = (ni >> 1) * 16 + (ni & 1) * 8 + (lane & 3) * 2;
        *(float2*)(cp + r0 * 64 + d) = make_float2(acc[ni][0], acc[ni][1]);
        *(float2*)(cp + (r0 + 8) * 64 + d) = make_float2(acc[ni][2], acc[ni][3]);
    }
}

// ---------------------------------------------------------------------------
// ctx finish: ctxh[bh][e][d] = fp16( 0.125/ksum[d] * sum_seg ctxp )
// ---------------------------------------------------------------------------
__global__ void k_ctx_fin() {
    int i = blockIdx.x * 256 + threadIdx.x;
    int bh = i >> 12, d = i & 63;
    float s = 0.f;
#pragma unroll
    for (int p = 0; p < NSEG; p++) s += g_ctxp[p][i];
    float inv = 0.125f / g_ksum[(bh >> 3) * 512 + (bh & 7) * 64 + d];
    g_ctxh[i] = __float2half_rn(s * inv);
}

// ---------------------------------------------------------------------------
// apply_mma: mh[b][n][h*64+e] = (1/qsum[n]) * sum_d eq[bh][n][d] * ctxh[bh][e][d]
// ---------------------------------------------------------------------------
__global__ __launch_bounds__(256, 2)
void k_apply_mma() {
    __shared__ __align__(16) char smc[24576];
    int nt = blockIdx.x, h = blockIdx.y, b = blockIdx.z;
    int n0 = nt * 128;
    const __half* Aq = g_qs + ((size_t)(b * HH + h) * SS + n0) * 64;
    const __half* Bc = g_ctxh + (size_t)(b * HH + h) * 4096;
    const float* qsp = g_qsum + (size_t)(b * HH + h) * SS + n0;

    uint32_t sA = smem_u32(smc), sB = sA + 16384;
    int tid = threadIdx.x, lane = tid & 31, wid = tid >> 5;

#pragma unroll
    for (int it = 0; it < 4; it++) {
        int id = it * 256 + tid;
        int row = id >> 3, j = id & 7;
        CP_ASYNC(sA + row * 128 + ((uint32_t)(j ^ (row & 7)) << 4),
                 Aq + (size_t)row * 64 + j * 8);
    }
#pragma unroll
    for (int it = 0; it < 2; it++) {
        int id = it * 256 + tid;
        int row = id >> 3, j = id & 7;
        CP_ASYNC(sB + row * 128 + ((uint32_t)(j ^ (row & 7)) << 4),
                 Bc + (size_t)row * 64 + j * 8);
    }
    CP_COMMIT();
    CP_WAIT(0);
    __syncthreads();

    int wm = (wid >> 1) * 32, wn = (wid & 1) * 32;
    int rA = wm + (lane & 7) + ((lane >> 3) & 1) * 8;
    int cA = lane >> 4;
    int rB = wn + (lane & 7) + ((lane >> 4) & 1) * 8;
    int cB = (lane >> 3) & 1;
    int swA = rA & 7, swB = rB & 7;

    float acc[2][4][4] = {};
#pragma unroll
    for (int ks = 0; ks < 4; ks++) {
        uint32_t a[2][4], bf[2][4];
        uint32_t kchA = ((uint32_t)(ks * 2 + cA) ^ swA) << 4;
        uint32_t kchB = ((uint32_t)(ks * 2 + cB) ^ swB) << 4;
#pragma unroll
        for (int mi = 0; mi < 2; mi++)
            LDSM4(a[mi], sA + (rA + mi * 16) * 128 + kchA);
#pragma unroll
        for (int p = 0; p < 2; p++)
            LDSM4(bf[p], sB + (rB + p * 16) * 128 + kchB);
#pragma unroll
        for (int mi = 0; mi < 2; mi++)
#pragma unroll
            for (int ni = 0; ni < 4; ni++)
                mma16(acc[mi][ni], a[mi], bf[ni >> 1] + (ni & 1) * 2);
    }

    __half* outp = g_mh + (size_t)b * SS * CC;
#pragma unroll
    for (int mi = 0; mi < 2; mi++) {
        int rl = wm + mi * 16 + (lane >> 2);
        float i0 = 1.f / qsp[rl];
        float i1 = 1.f / qsp[rl + 8];
        int r = n0 + rl;
#pragma unroll
        for (int ni = 0; ni < 4; ni++) {
            int c = h * 64 + wn + (ni >> 1) * 16 + (ni & 1) * 8 + (lane & 3) * 2;
            *(__half2*)(outp + (size_t)r * CC + c) =
                __floats2half2_rn(acc[mi][ni][0] * i0, acc[mi][ni][1] * i0);
            *(__half2*)(outp + (size_t)(r + 8) * CC + c) =
                __floats2half2_rn(acc[mi][ni][2] * i1, acc[mi][ni][3] * i1);
        }
    }
}

// ---------------------------------------------------------------------------
// K5: out = rmsnorm( wo @ mh^T + bias ) * gamma2
// ---------------------------------------------------------------------------
__global__ __launch_bounds__(512, 1)
void k_ogemm(const __half* __restrict__ A, const __half* __restrict__ Bg,
             float* __restrict__ out, const float* __restrict__ bias,
             const float* __restrict__ gamma2) {
    extern __shared__ char smc[];
    const int STG = 36864;
    uint32_t sbase = smem_u32(smc);
    float* colsq = (float*)(smc + 3 * STG);
    float* csc   = colsq + 64;

    int tid = threadIdx.x, lane = tid & 31, wid = tid >> 5;
    int b = blockIdx.y, n0 = blockIdx.x * 64;
    const __half* Bb = Bg + ((size_t)b * SS + n0) * CC;

    if (tid < 64) colsq[tid] = 0.f;

    auto issue = [&](int kc, int buf) {
        uint32_t base = sbase + buf * STG;
#pragma unroll
        for (int it = 0; it < 4; it++) {
            int id = it * 512 + tid;
            int row = id >> 2, j = id & 3;
            uint32_t dst = base + row * 64 + (((uint32_t)j ^ ((row >> 1) & 3)) << 4);
            CP_ASYNC(dst, A + (size_t)row * CC + kc * 32 + j * 8);
        }
        if (tid < 256) {
            int row = tid >> 2, j = tid & 3;
            uint32_t dst = base + 32768 + row * 64 + (((uint32_t)j ^ ((row >> 1) & 3)) << 4);
            CP_ASYNC(dst, Bb + (size_t)row * CC + kc * 32 + j * 8);
        }
    };

#pragma unroll
    for (int s = 0; s < NSTG - 1; s++) { issue(s, s); CP_COMMIT(); }

    int wm = (wid >> 1) * 64, wn = (wid & 1) * 32;
    int rA = wm + (lane & 7) + ((lane >> 3) & 1) * 8;
    int cA = (lane >> 4);
    int rB = wn + (lane & 7) + ((lane >> 4) & 1) * 8;
    int cB = (lane >> 3) & 1;
    int swA = (rA >> 1) & 3, swB = (rB >> 1) & 3;

    float acc[4][4][4] = {};
    const int NC = CC / 32;

    for (int kc = 0; kc < NC; kc++) {
        CP_WAIT(NSTG - 2);
        __syncthreads();
        if (kc + NSTG - 1 < NC) issue(kc + NSTG - 1, (kc + NSTG - 1) % NSTG);
        CP_COMMIT();
        uint32_t bufA = sbase + (kc % NSTG) * STG;
        uint32_t bufB = bufA + 32768;
#pragma unroll
        for (int ks = 0; ks < 2; ks++) {
            uint32_t a[4][4], bf[2][4];
            uint32_t kchA = ((uint32_t)(ks * 2 + cA) ^ swA) << 4;
            uint32_t kchB = ((uint32_t)(ks * 2 + cB) ^ swB) << 4;
#pragma unroll
            for (int mi = 0; mi < 4; mi++)
                LDSM4(a[mi], bufA + (rA + mi * 16) * 64 + kchA);
#pragma unroll
            for (int p = 0; p < 2; p++)
                LDSM4(bf[p], bufB + (rB + p * 16) * 64 + kchB);
#pragma unroll
            for (int mi = 0; mi < 4; mi++)
#pragma unroll
                for (int ni = 0; ni < 4; ni++)
                    mma16(acc[mi][ni], a[mi], bf[ni >> 1] + (ni & 1) * 2);
        }
    }

    float bi0[4], bi1[4];
#pragma unroll
    for (int mi = 0; mi < 4; mi++) {
        bi0[mi] = bias[wm + mi * 16 + (lane >> 2)];
        bi1[mi] = bias[wm + mi * 16 + (lane >> 2) + 8];
    }
#pragma unroll
    for (int ni = 0; ni < 4; ni++) {
        float l0 = 0.f, l1 = 0.f;
#pragma unroll
        for (int mi = 0; mi < 4; mi++) {
            acc[mi][ni][0] += bi0[mi]; acc[mi][ni][1] += bi0[mi];
            acc[mi][ni][2] += bi1[mi]; acc[mi][ni][3] += bi1[mi];
            l0 += acc[mi][ni][0] * acc[mi][ni][0] + acc[mi][ni][2] * acc[mi][ni][2];
            l1 += acc[mi][ni][1] * acc[mi][ni][1] + acc[mi][ni][3] * acc[mi][ni][3];
        }
#pragma unroll
        for (int o = 4; o <= 16; o <<= 1) {
            l0 += __shfl_xor_sync(0xFFFFFFFFu, l0, o);
            l1 += __shfl_xor_sync(0xFFFFFFFFu, l1, o);
        }
        if ((lane >> 2) == 0) {
            int cloc = wn + (ni >> 1) * 16 + (ni & 1) * 8 + (lane & 3) * 2;
            atomicAdd(colsq + cloc, l0);
            atomicAdd(colsq + cloc + 1, l1);
        }
    }
    __syncthreads();
    if (tid < 64)
        csc[tid] = 22.62741699796952f / fmaxf(sqrtf(colsq[tid]), 1e-12f);
    __syncthreads();

    float* Cd = out + (size_t)b * CC * SS + n0;
#pragma unroll
    for (int mi = 0; mi < 4; mi++) {
        int r0 = wm + mi * 16 + (lane >> 2);
        float g0 = gamma2[r0], g1 = gamma2[r0 + 8];
#pragma unroll
        for (int ni = 0; ni < 4; ni++) {
            int cloc = wn + (ni >> 1) * 16 + (ni & 1) * 8 + (lane & 3) * 2;
            float s0 = csc[cloc], s1 = csc[cloc + 1];
            *(float2*)(Cd + (size_t)r0 * SS + cloc) =
                make_float2(acc[mi][ni][0] * s0 * g0, acc[mi][ni][1] * s1 * g0);
            *(float2*)(Cd + (size_t)(r0 + 8) * SS + cloc) =
                make_float2(acc[mi][ni][2] * s0 * g1, acc[mi][ni][3] * s1 * g1);
        }
    }
}

// ---------------------------------------------------------------------------
extern "C" void kernel_launch(void* const* d_in, const int* in_sizes, int n_in,
                              void* d_out, int out_size) {
    const float* x      = (const float*)d_in[0];
    const float* gamma1 = (const float*)d_in[1];
    const float* w_qkv  = (const float*)d_in[2];
    const float* w_out  = (const float*)d_in[3];
    const float* b_out  = (const float*)d_in[4];
    const float* gamma2 = (const float*)d_in[5];
    float* out = (float*)d_out;

    __half *woh_p, *mh_p;
    cudaGetSymbolAddress((void**)&woh_p, g_woh);
    cudaGetSymbolAddress((void**)&mh_p,  g_mh);

    const int SMEM_NT = (512 * 33 + 32) * 4;
    const int SMEM_G1 = NSTG * 32768;
    const int SMEM_CX = 65536;
    const int SMEM_G5 = NSTG * 36864 + 512;
    cudaFuncSetAttribute(k_normT,   cudaFuncAttributeMaxDynamicSharedMemorySize, SMEM_NT);
    cudaFuncSetAttribute(k_hgemm,   cudaFuncAttributeMaxDynamicSharedMemorySize, SMEM_G1);
    cudaFuncSetAttribute(k_ctx_mma, cudaFuncAttributeMaxDynamicSharedMemorySize, SMEM_CX);
    cudaFuncSetAttribute(k_ogemm,   cudaFuncAttributeMaxDynamicSharedMemorySize, SMEM_G5);

    k_prep<<<(QKV * CC + CC * CC) / 256, 256>>>(w_qkv, gamma1, w_out);
    k_normT<<<dim3(SS / 32, BB), 256, SMEM_NT>>>(x);
    // K1: qkv GEMM (128x128) + fused epilogues
    k_hgemm<<<dim3(SS / 128, QKV / 128, BB), 256, SMEM_G1>>>();
    // fold k row-sum partials (parallel)
    k_ksumf<<<BB * 512 * 8 / 256, 256>>>();
    // ctx via tensor cores (8-way split-K, 2 chunks per block) + finish
    k_ctx_mma<<<dim3(NSEG, HH, BB), 128, SMEM_CX>>>();
    k_ctx_fin<<<BB * HH * 4096 / 256, 256>>>();
    // apply exp(q) to ctx, normalize by qsum -> mh
    k_apply_mma<<<dim3(SS / 128, HH, BB), 256>>>();
    // K5: fused out-proj + bias + rms-norm
    k_ogemm<<<dim3(SS / 64, BB), 512, SMEM_G5>>>(woh_p, mh_p, out, b_out, gamma2);
}